// round 10
// baseline (speedup 1.0000x reference)
#include <cuda_runtime.h>

#define F    64
#define WIN  16
#define NEG  0.2f
#define BT   64
#define ROWS (BT + WIN - 1)   /* 79 */
#define OPAD 68               /* halo pitch   */
#define MTP  68               /* mtx pitch    */

__global__ __launch_bounds__(256)
void gat_fused(const float* __restrict__ ori,
               const float* __restrict__ Wfc,
               const float* __restrict__ al,
               const float* __restrict__ ar,
               const float* __restrict__ bias,
               float* __restrict__ out, int T)
{
    // uni: halo tile [ROWS][OPAD] -> mtx [F][MTP] -> GEMM partials [4096]
    __shared__ __align__(16) float uni[ROWS * OPAD];   // 21488 B
    __shared__ __align__(16) float Wsh[F][F];          // 16384 B
    __shared__ __align__(16) float walsh[F], warsh[F], bsh[F];
    __shared__ __align__(16) float alsh[F],  arsh[F];
    __shared__ float elsh[ROWS], ersh[ROWS];

    const int tid = threadIdx.x;
    const int t0  = blockIdx.x * BT;

    // ---- stage W + vectors + clamped x halo ----
    for (int i = tid; i < F * F / 4; i += 256)
        ((float4*)Wsh)[i] = ((const float4*)Wfc)[i];
    if (tid < F) { alsh[tid] = al[tid]; arsh[tid] = ar[tid]; bsh[tid] = bias[tid]; }
    for (int i = tid; i < ROWS * 16; i += 256) {
        int r  = i >> 4;
        int c4 = i & 15;
        int s  = t0 - (WIN - 1) + r;
        s = s < 0 ? 0 : (s > T - 1 ? T - 1 : s);
        *(float4*)&uni[r * OPAD + 4 * c4] = ((const float4*)(ori + (size_t)s * F))[c4];
    }
    __syncthreads();

    // ---- wal = W @ attn_l, war = W @ attn_r (diagonal reads) ----
    if (tid < 2 * F) {
        int  f   = tid & 63;
        bool isl = tid < F;
        const float* av = isl ? alsh : arsh;
        float s = 0.f;
        #pragma unroll 8
        for (int i = 0; i < F; i++) {
            int o = (f + i) & 63;
            s += Wsh[f][o] * av[o];
        }
        if (isl) walsh[f] = s; else warsh[f] = s;
    }
    __syncthreads();

    // ---- scores el/er per halo row (16-lane groups, UNIFORM trips for shfl) ----
    #pragma unroll
    for (int it = 0; it < (ROWS * 16 + 255) / 256; it++) {   // 5
        int  i0    = tid + it * 256;
        bool valid = i0 < ROWS * 16;
        int  i     = valid ? i0 : ROWS * 16 - 1;
        int  r     = i >> 4;
        int  c4    = i & 15;
        float4 xv = *(const float4*)&uni[r * OPAD + 4 * c4];
        float4 wl = *(const float4*)&walsh[4 * c4];
        float4 wr = *(const float4*)&warsh[4 * c4];
        float pl = xv.x*wl.x + xv.y*wl.y + xv.z*wl.z + xv.w*wl.w;
        float pr = xv.x*wr.x + xv.y*wr.y + xv.z*wr.z + xv.w*wr.w;
        #pragma unroll
        for (int off = 8; off; off >>= 1) {
            pl += __shfl_xor_sync(0xffffffffu, pl, off);
            pr += __shfl_xor_sync(0xffffffffu, pr, off);
        }
        if (valid && c4 == 0) { elsh[r] = pl; ersh[r] = pr; }
    }
    __syncthreads();

    // ---- mix: group g owns j = 4g..4g+3; single sweep over 19 rows ----
    const int g  = tid >> 4;
    const int gl = tid & 15;

    float elr[WIN + 3];                       // el for rows 4g .. 4g+18
    #pragma unroll
    for (int d = 0; d < WIN + 3; d++) elr[d] = elsh[4 * g + d];
    float erv[4], mj[4], inv[4];
    #pragma unroll
    for (int jj = 0; jj < 4; jj++) erv[jj] = ersh[4 * g + jj + WIN - 1];
    #pragma unroll
    for (int jj = 0; jj < 4; jj++) {
        float m = -1e30f;
        #pragma unroll
        for (int u = 0; u < WIN; u++) {
            float e = elr[jj + u] + erv[jj];
            e = (e > 0.f) ? e : NEG * e;
            m = fmaxf(m, e);
        }
        float s = 0.f;
        #pragma unroll
        for (int u = 0; u < WIN; u++) {
            float e = elr[jj + u] + erv[jj];
            e = (e > 0.f) ? e : NEG * e;
            s += __expf(e - m);
        }
        mj[jj]  = m;
        inv[jj] = 1.f / s;
    }

    float mv[4][4];
    #pragma unroll
    for (int jj = 0; jj < 4; jj++)
        #pragma unroll
        for (int q = 0; q < 4; q++) mv[jj][q] = 0.f;

    #pragma unroll
    for (int d = 0; d < WIN + 3; d++) {       // row h = 4g+d, read ONCE
        float4 xv = *(const float4*)&uni[(4 * g + d) * OPAD + 4 * gl];
        float xq[4] = {xv.x, xv.y, xv.z, xv.w};
        #pragma unroll
        for (int jj = 0; jj < 4; jj++) {
            if (d >= jj && d - jj < WIN) {    // static predicate (both loops unrolled)
                float e = elr[d] + erv[jj];
                e = (e > 0.f) ? e : NEG * e;
                float w = __expf(e - mj[jj]);
                #pragma unroll
                for (int q = 0; q < 4; q++) mv[jj][q] += w * xq[q];
            }
        }
    }
    #pragma unroll
    for (int jj = 0; jj < 4; jj++)
        #pragma unroll
        for (int q = 0; q < 4; q++) mv[jj][q] *= inv[jj];

    __syncthreads();   // halo reads done -> uni becomes mtx [F][MTP] (k-major)

    // ---- transposed store: aligned float4 along 4 consecutive j ----
    #pragma unroll
    for (int q = 0; q < 4; q++) {             // feature f = 4*gl + q
        float4 sv = make_float4(mv[0][q], mv[1][q], mv[2][q], mv[3][q]);
        *(float4*)&uni[(4 * gl + q) * MTP + 4 * g] = sv;
    }
    __syncthreads();

    // ---- GEMM: 32x32 warp tiles, 2-way k-split ----
    const int lane = tid & 31;
    const int wq   = tid >> 5;
    const int wt   = wq & 3;
    const int R0   = (wt >> 1) * 32;
    const int C0   = (wt & 1) * 32;
    const int kb   = (wq >> 2) * 32;
    const int rg   = lane & 7;                // row group: rows R0+4rg..+3
    const int cg   = lane >> 3;               // col group: cols C0+8cg..+7

    float acc[4][8];
    #pragma unroll
    for (int r = 0; r < 4; r++)
        #pragma unroll
        for (int c = 0; c < 8; c++) acc[r][c] = 0.f;

    #pragma unroll 4
    for (int kk = 0; kk < 32; kk++) {
        int k = kb + kk;
        float4 xv = *(const float4*)&uni[k * MTP + R0 + 4 * rg];   // 128B distinct/warp
        float4 wa = *(const float4*)&Wsh[k][C0 + 8 * cg];
        float4 wb = *(const float4*)&Wsh[k][C0 + 8 * cg + 4];
        float xr[4] = {xv.x, xv.y, xv.z, xv.w};
        float wv[8] = {wa.x, wa.y, wa.z, wa.w, wb.x, wb.y, wb.z, wb.w};
        #pragma unroll
        for (int r = 0; r < 4; r++) {
            float x = xr[r];
            #pragma unroll
            for (int c = 0; c < 8; c++) acc[r][c] += x * wv[c];
        }
    }
    __syncthreads();   // all mtx reads done -> uni becomes partial buffer

    if (wq >= 4) {     // k=32..63 halves: conflict-free strided store
        float* part = uni + (wq - 4) * 1024;
        #pragma unroll
        for (int r = 0; r < 4; r++)
            #pragma unroll
            for (int c = 0; c < 8; c++)
                part[(r * 8 + c) * 32 + lane] = acc[r][c];
    }
    __syncthreads();

    if (wq < 4) {      // merge + epilogue
        const float* part = uni + wq * 1024;
        #pragma unroll
        for (int r = 0; r < 4; r++)
            #pragma unroll
            for (int c = 0; c < 8; c++)
                acc[r][c] += part[(r * 8 + c) * 32 + lane];

        float4 b0 = *(const float4*)&bsh[C0 + 8 * cg];
        float4 b1 = *(const float4*)&bsh[C0 + 8 * cg + 4];
        #pragma unroll
        for (int r = 0; r < 4; r++) {
            int t = t0 + R0 + 4 * rg + r;
            if (t < T) {
                float4 o0 = make_float4(acc[r][0] + b0.x, acc[r][1] + b0.y,
                                        acc[r][2] + b0.z, acc[r][3] + b0.w);
                float4 o1 = make_float4(acc[r][4] + b1.x, acc[r][5] + b1.y,
                                        acc[r][6] + b1.z, acc[r][7] + b1.w);
                *(float4*)&out[(size_t)t * F + C0 + 8 * cg]     = o0;
                *(float4*)&out[(size_t)t * F + C0 + 8 * cg + 4] = o1;
            }
        }
    }
}

extern "C" void kernel_launch(void* const* d_in, const int* in_sizes, int n_in,
                              void* d_out, int out_size) {
    const float* ori  = (const float*)d_in[0];
    const float* Wfc  = (const float*)d_in[1];
    const float* al   = (const float*)d_in[2];
    const float* ar   = (const float*)d_in[3];
    const float* bias = (const float*)d_in[4];
    float* out = (float*)d_out;
    int T = in_sizes[0] / F;
    gat_fused<<<(T + BT - 1) / BT, 256>>>(ori, Wfc, al, ar, bias, out, T);
}

// round 11
// speedup vs baseline: 1.0088x; 1.0088x over previous
#include <cuda_runtime.h>

#define F    64
#define WIN  16
#define NEG  0.2f
#define BT   64
#define ROWS (BT + WIN - 1)   /* 79 */
#define OPAD 68               /* halo pitch */
#define MTP  68               /* mtx pitch  */

__global__ __launch_bounds__(256)
void gat_fused(const float* __restrict__ ori,
               const float* __restrict__ Wfc,
               const float* __restrict__ al,
               const float* __restrict__ ar,
               const float* __restrict__ bias,
               float* __restrict__ out, int T)
{
    // uni: halo tile [ROWS][OPAD] -> mtx [F][MTP]
    __shared__ __align__(16) float uni[ROWS * OPAD];   // 21488 B
    __shared__ __align__(16) float Wsh[F][F];          // 16384 B
    __shared__ __align__(16) float walsh[F], warsh[F], bsh[F];
    __shared__ __align__(16) float alsh[F],  arsh[F];
    __shared__ float elsh[ROWS], ersh[ROWS];

    const int tid = threadIdx.x;
    const int t0  = blockIdx.x * BT;

    // ---- stage W + vectors + clamped x halo ----
    for (int i = tid; i < F * F / 4; i += 256)
        ((float4*)Wsh)[i] = ((const float4*)Wfc)[i];
    if (tid < F) { alsh[tid] = al[tid]; arsh[tid] = ar[tid]; bsh[tid] = bias[tid]; }
    for (int i = tid; i < ROWS * 16; i += 256) {
        int r  = i >> 4;
        int c4 = i & 15;
        int s  = t0 - (WIN - 1) + r;
        s = s < 0 ? 0 : (s > T - 1 ? T - 1 : s);
        *(float4*)&uni[r * OPAD + 4 * c4] = ((const float4*)(ori + (size_t)s * F))[c4];
    }
    __syncthreads();

    // ---- wal = W @ attn_l, war = W @ attn_r (diagonal reads) ----
    if (tid < 2 * F) {
        int  f   = tid & 63;
        bool isl = tid < F;
        const float* av = isl ? alsh : arsh;
        float s = 0.f;
        #pragma unroll 8
        for (int i = 0; i < F; i++) {
            int o = (f + i) & 63;
            s += Wsh[f][o] * av[o];
        }
        if (isl) walsh[f] = s; else warsh[f] = s;
    }
    __syncthreads();

    // ---- scores el/er per halo row (16-lane groups, UNIFORM trips for shfl) ----
    #pragma unroll
    for (int it = 0; it < (ROWS * 16 + 255) / 256; it++) {   // 5
        int  i0    = tid + it * 256;
        bool valid = i0 < ROWS * 16;
        int  i     = valid ? i0 : ROWS * 16 - 1;
        int  r     = i >> 4;
        int  c4    = i & 15;
        float4 xv = *(const float4*)&uni[r * OPAD + 4 * c4];
        float4 wl = *(const float4*)&walsh[4 * c4];
        float4 wr = *(const float4*)&warsh[4 * c4];
        float pl = xv.x*wl.x + xv.y*wl.y + xv.z*wl.z + xv.w*wl.w;
        float pr = xv.x*wr.x + xv.y*wr.y + xv.z*wr.z + xv.w*wr.w;
        #pragma unroll
        for (int off = 8; off; off >>= 1) {
            pl += __shfl_xor_sync(0xffffffffu, pl, off);
            pr += __shfl_xor_sync(0xffffffffu, pr, off);
        }
        if (valid && c4 == 0) { elsh[r] = pl; ersh[r] = pr; }
    }
    __syncthreads();

    // ---- mix: group g owns j = 4g..4g+3; two sweeps over 19 rows, low-reg ----
    const int g  = tid >> 4;
    const int gl = tid & 15;

    float erv[4], mj[4], sj[4];
    #pragma unroll
    for (int jj = 0; jj < 4; jj++) {
        erv[jj] = ersh[4 * g + jj + WIN - 1];
        mj[jj]  = -1e30f;
        sj[jj]  = 0.f;
    }
    // pass 1: running max (el read broadcast from smem, no reg array)
    #pragma unroll
    for (int d = 0; d < WIN + 3; d++) {
        float el = elsh[4 * g + d];
        #pragma unroll
        for (int jj = 0; jj < 4; jj++) {
            if (d >= jj && d - jj < WIN) {
                float e = el + erv[jj];
                e = (e > 0.f) ? e : NEG * e;
                mj[jj] = fmaxf(mj[jj], e);
            }
        }
    }
    // pass 2: unnormalized accumulate + sum in one sweep
    float mv[4][4];
    #pragma unroll
    for (int jj = 0; jj < 4; jj++)
        #pragma unroll
        for (int q = 0; q < 4; q++) mv[jj][q] = 0.f;

    #pragma unroll
    for (int d = 0; d < WIN + 3; d++) {
        float  el = elsh[4 * g + d];
        float4 xv = *(const float4*)&uni[(4 * g + d) * OPAD + 4 * gl];
        #pragma unroll
        for (int jj = 0; jj < 4; jj++) {
            if (d >= jj && d - jj < WIN) {
                float e = el + erv[jj];
                e = (e > 0.f) ? e : NEG * e;
                float w = __expf(e - mj[jj]);
                sj[jj] += w;
                mv[jj][0] += w * xv.x;
                mv[jj][1] += w * xv.y;
                mv[jj][2] += w * xv.z;
                mv[jj][3] += w * xv.w;
            }
        }
    }
    #pragma unroll
    for (int jj = 0; jj < 4; jj++) {
        float inv = 1.f / sj[jj];
        #pragma unroll
        for (int q = 0; q < 4; q++) mv[jj][q] *= inv;
    }
    __syncthreads();   // halo reads done -> uni becomes mtx [F][MTP] (k-major)

    // ---- transposed store: aligned float4 along 4 consecutive j ----
    #pragma unroll
    for (int q = 0; q < 4; q++) {             // feature f = 4*gl + q
        float4 sv = make_float4(mv[0][q], mv[1][q], mv[2][q], mv[3][q]);
        *(float4*)&uni[(4 * gl + q) * MTP + 4 * g] = sv;
    }
    __syncthreads();

    // ---- GEMM: 32x16 warp tiles, full k per warp (no split, no merge) ----
    const int lane = tid & 31;
    const int wq   = tid >> 5;
    const int R0   = (wq >> 2) * 32;          // 2 row halves
    const int C0   = (wq & 3) * 16;           // 4 col quarters
    const int rg   = lane & 7;                // rows R0+4rg..+3
    const int cg   = lane >> 3;               // cols C0+4cg..+3

    float acc[4][4];
    #pragma unroll
    for (int r = 0; r < 4; r++)
        #pragma unroll
        for (int c = 0; c < 4; c++) acc[r][c] = 0.f;

    #pragma unroll 8
    for (int k = 0; k < F; k++) {
        float4 xv = *(const float4*)&uni[k * MTP + R0 + 4 * rg];   // 128B distinct/warp
        float4 wv = *(const float4*)&Wsh[k][C0 + 4 * cg];          // 64B distinct/warp
        float xr[4] = {xv.x, xv.y, xv.z, xv.w};
        float wc[4] = {wv.x, wv.y, wv.z, wv.w};
        #pragma unroll
        for (int r = 0; r < 4; r++) {
            float x = xr[r];
            #pragma unroll
            for (int c = 0; c < 4; c++) acc[r][c] += x * wc[c];
        }
    }

    // ---- epilogue straight from registers: float4 per row ----
    float4 bv = *(const float4*)&bsh[C0 + 4 * cg];
    #pragma unroll
    for (int r = 0; r < 4; r++) {
        int t = t0 + R0 + 4 * rg + r;
        if (t < T) {
            float4 o = make_float4(acc[r][0] + bv.x, acc[r][1] + bv.y,
                                   acc[r][2] + bv.z, acc[r][3] + bv.w);
            *(float4*)&out[(size_t)t * F + C0 + 4 * cg] = o;
        }
    }
}

extern "C" void kernel_launch(void* const* d_in, const int* in_sizes, int n_in,
                              void* d_out, int out_size) {
    const float* ori  = (const float*)d_in[0];
    const float* Wfc  = (const float*)d_in[1];
    const float* al   = (const float*)d_in[2];
    const float* ar   = (const float*)d_in[3];
    const float* bias = (const float*)d_in[4];
    float* out = (float*)d_out;
    int T = in_sizes[0] / F;
    gat_fused<<<(T + BT - 1) / BT, 256>>>(ori, Wfc, al, ar, bias, out, T);
}